// round 9
// baseline (speedup 1.0000x reference)
#include <cuda_runtime.h>
#include <math_constants.h>

// Density-aware Chamfer loss, B=4, N=8192, 3D fp32.
// Base = R2 (best: monolithic 128KB smem ref cloud, TPB=256, QPT=2, 1 CTA/SM,
// 128 CTAs, inline histogram). Changes:
//   - 4 min-accumulator banks per (k, half): 16 independent FMNMX chains
//     (was 4 serial chains of depth 16) to cut dependency-stall exposure.
//   - GROUP 32 -> 64: half the group-select bookkeeping; rescan still cheap.
//   - finalize_partial grid 64 -> 256 (latency-bound tail).
//  zero_kernel      : clear counts
//  nn_kernel        : packed fma.rn.f32x2; banked group-min (64) +
//                     winning-group bit-exact rescan; g_idx + atomics inline.
//  finalize_partial : 256-block gather/exp/weight partial sums
//  finalize_final   : fixed-order merge -> out[b]

#define B_CONST   4
#define N_CONST   8192
#define TPB       256
#define QPT       2
#define QPC       (TPB * QPT)          // 512 queries / CTA
#define QCHUNKS   (N_CONST / QPC)      // 16
#define GROUP     64
#define JPG       (GROUP / 2)          // 32 j-pairs per group
#define NGROUPS   (N_CONST / GROUP)    // 128
#define SMEM_BYTES (N_CONST * 4 * sizeof(float))   // 131072

#define FIN_TPB   256
#define FIN_EPB   256
#define FIN_BLOCKS (2 * B_CONST * N_CONST / FIN_EPB)  // 256
#define FIN_CPD   (N_CONST / FIN_EPB)                 // 32 chunks per db

__device__ int   g_idx [2 * B_CONST * N_CONST];
__device__ int   g_cnt [2 * B_CONST * N_CONST];
__device__ float g_part[FIN_BLOCKS];

__global__ void zero_kernel() {
    int gid = blockIdx.x * blockDim.x + threadIdx.x;
    if (gid < 2 * B_CONST * N_CONST) g_cnt[gid] = 0;
}

// db = dir*B + b.  dir 0: queries = gts, refs = preds. dir 1: swapped.
__global__ __launch_bounds__(TPB, 1) void nn_kernel(const float* __restrict__ gts,
                                                    const float* __restrict__ preds) {
    extern __shared__ float s_tile[];   // jj*8 -> rx0 rx1 ry0 ry1 rz0 rz1 rw0 rw1

    const int db  = blockIdx.y;
    const int b   = db & (B_CONST - 1);
    const int dir = db >> 2;
    const float* __restrict__ qptr = (dir == 0) ? gts : preds;
    const float* __restrict__ rptr = (dir == 0) ? preds : gts;

    // ---- load whole ref cloud into interleaved smem ----
    const float* rbase = rptr + (long)b * N_CONST * 3;
    for (int j = threadIdx.x; j < N_CONST; j += TPB) {
        float x = rbase[3 * j + 0];
        float y = rbase[3 * j + 1];
        float z = rbase[3 * j + 2];
        int jj = j >> 1, h = j & 1;
        float* p = s_tile + jj * 8;
        p[0 + h] = x;
        p[2 + h] = y;
        p[4 + h] = z;
        p[6 + h] = x * x + y * y + z * z;
    }
    __syncthreads();

    // ---- per-thread queries: packed-duplicated (-2*q) ----
    const int q0 = blockIdx.x * QPC + threadIdx.x;
    const float* qbase = qptr + (long)b * N_CONST * 3;

    float qxs[QPT], qys[QPT], qzs[QPT];
    unsigned long long qx2[QPT], qy2[QPT], qz2[QPT];
    float best[QPT];
    int   gidw[QPT];
    float mE[QPT][4], mO[QPT][4];   // 4 banks x (even/odd lane) independent chains

    #pragma unroll
    for (int k = 0; k < QPT; k++) {
        int q = q0 + k * TPB;
        qxs[k] = -2.0f * qbase[3 * q + 0];
        qys[k] = -2.0f * qbase[3 * q + 1];
        qzs[k] = -2.0f * qbase[3 * q + 2];
        asm("mov.b64 %0, {%1, %1};" : "=l"(qx2[k]) : "f"(qxs[k]));
        asm("mov.b64 %0, {%1, %1};" : "=l"(qy2[k]) : "f"(qys[k]));
        asm("mov.b64 %0, {%1, %1};" : "=l"(qz2[k]) : "f"(qzs[k]));
        best[k] = CUDART_INF_F;
        gidw[k] = 0;
        #pragma unroll
        for (int t = 0; t < 4; t++) { mE[k][t] = CUDART_INF_F; mO[k][t] = CUDART_INF_F; }
    }

    // ---- main scan: groups of 64 refs, packed over j-pairs, banked mins ----
    for (int g = 0; g < NGROUPS; g++) {
        const float* gb = s_tile + g * JPG * 8;
        #pragma unroll 8
        for (int jj = 0; jj < JPG; jj++) {
            ulonglong2 A  = *(const ulonglong2*)(gb + jj * 8);      // {rx2, ry2}
            ulonglong2 Bv = *(const ulonglong2*)(gb + jj * 8 + 4);  // {rz2, rw2}
            const int bank = jj & 3;
            #pragma unroll
            for (int k = 0; k < QPT; k++) {
                float tlo, thi;
                asm("{\n\t"
                    ".reg .b64 t;\n\t"
                    "fma.rn.f32x2 t, %2, %3, %4;\n\t"
                    "fma.rn.f32x2 t, %5, %6, t;\n\t"
                    "fma.rn.f32x2 t, %7, %8, t;\n\t"
                    "mov.b64 {%0, %1}, t;\n\t"
                    "}"
                    : "=f"(tlo), "=f"(thi)
                    : "l"(qx2[k]), "l"(A.x), "l"(Bv.y),
                      "l"(qy2[k]), "l"(A.y),
                      "l"(qz2[k]), "l"(Bv.x));
                mE[k][bank] = fminf(mE[k][bank], tlo);
                mO[k][bank] = fminf(mO[k][bank], thi);
            }
        }
        #pragma unroll
        for (int k = 0; k < QPT; k++) {
            // tree-reduce 8 banks (min is order-independent on finite data)
            float m0 = fminf(mE[k][0], mE[k][1]);
            float m1 = fminf(mE[k][2], mE[k][3]);
            float m2 = fminf(mO[k][0], mO[k][1]);
            float m3 = fminf(mO[k][2], mO[k][3]);
            float m  = fminf(fminf(m0, m1), fminf(m2, m3));
            if (m < best[k]) { best[k] = m; gidw[k] = g; }  // strict <: earliest group wins
            #pragma unroll
            for (int t = 0; t < 4; t++) { mE[k][t] = CUDART_INF_F; mO[k][t] = CUDART_INF_F; }
        }
    }

    // ---- rescan winning group: bit-exact recompute, first index wins ----
    #pragma unroll
    for (int k = 0; k < QPT; k++) {
        const int base = gidw[k] * GROUP;
        int idx = 0x7fffffff;
        #pragma unroll 8
        for (int j = 0; j < GROUP; j++) {
            int jj = (base + j) >> 1, h = (base + j) & 1;
            const float* p = s_tile + jj * 8;
            float t = fmaf(qxs[k], p[0 + h], p[6 + h]);
            t = fmaf(qys[k], p[2 + h], t);
            t = fmaf(qzs[k], p[4 + h], t);
            if (t == best[k]) idx = min(idx, base + j);
        }
        int q = q0 + k * TPB;
        g_idx[db * N_CONST + q] = idx;
        atomicAdd(&g_cnt[db * N_CONST + idx], 1);
    }
}

__global__ __launch_bounds__(FIN_TPB) void finalize_partial(const float* __restrict__ gts,
                                                            const float* __restrict__ preds) {
    __shared__ float ssum[FIN_TPB];
    const int e = blockIdx.x * FIN_EPB + threadIdx.x;   // FIN_EPB == FIN_TPB
    const int db = e / N_CONST;
    const int q  = e - db * N_CONST;
    const int b  = db & (B_CONST - 1);
    const int dir = db >> 2;
    const float* qptr = (dir == 0) ? gts : preds;
    const float* rptr = (dir == 0) ? preds : gts;
    const float* qb = qptr + (long)b * N_CONST * 3;
    const float* rb = rptr + (long)b * N_CONST * 3;

    int id = g_idx[e];
    float dx = qb[3 * q + 0] - rb[3 * id + 0];
    float dy = qb[3 * q + 1] - rb[3 * id + 1];
    float dz = qb[3 * q + 2] - rb[3 * id + 2];
    float d  = dx * dx + dy * dy + dz * dz;
    float c  = (float)g_cnt[db * N_CONST + id];
    float acc = 1.0f - expf(-d) / (c + 1e-6f);   // ALPHA=1, N_LAMBDA=1, frac=1

    ssum[threadIdx.x] = acc;
    __syncthreads();
    for (int off = FIN_TPB / 2; off > 0; off >>= 1) {
        if (threadIdx.x < off) ssum[threadIdx.x] += ssum[threadIdx.x + off];
        __syncthreads();
    }
    if (threadIdx.x == 0) g_part[blockIdx.x] = ssum[0];
}

__global__ void finalize_final(float* __restrict__ out) {
    int b = threadIdx.x;
    if (b >= B_CONST) return;
    float s = 0.0f;
    #pragma unroll
    for (int dir = 0; dir < 2; dir++) {
        int db = dir * B_CONST + b;
        #pragma unroll
        for (int c = 0; c < FIN_CPD; c++)
            s += g_part[db * FIN_CPD + c];
    }
    out[b] = s / (2.0f * (float)N_CONST);
}

extern "C" void kernel_launch(void* const* d_in, const int* in_sizes, int n_in,
                              void* d_out, int out_size) {
    const float* gts   = (const float*)d_in[0];
    const float* preds = (const float*)d_in[1];
    float* out = (float*)d_out;

    cudaFuncSetAttribute(nn_kernel, cudaFuncAttributeMaxDynamicSharedMemorySize, SMEM_BYTES);

    zero_kernel<<<(2 * B_CONST * N_CONST + 255) / 256, 256>>>();
    nn_kernel<<<dim3(QCHUNKS, 2 * B_CONST), TPB, SMEM_BYTES>>>(gts, preds);
    finalize_partial<<<FIN_BLOCKS, FIN_TPB>>>(gts, preds);
    finalize_final<<<1, 32>>>(out);
}